// round 12
// baseline (speedup 1.0000x reference)
#include <cuda_runtime.h>

#define BB 8
#define NN 8192
#define MM 1024
#define KK 32
#define CC 64
#define CIN 67
#define R2 0.16f

typedef unsigned long long ull;

// one counter per 128B line to kill L2-slice contention from pollers
__device__ int g_prog[BB * 32];

// ---- packed f32x2 helpers (sm_100+: only add/mul/fma exist packed) ----
__device__ __forceinline__ ull pk2(float a, float b) {
    ull r; asm("mov.b64 %0,{%1,%2};" : "=l"(r) : "f"(a), "f"(b)); return r;
}
__device__ __forceinline__ void upk2(ull v, float& a, float& b) {
    asm("mov.b64 {%0,%1},%2;" : "=f"(a), "=f"(b) : "l"(v));
}
__device__ __forceinline__ ull add2(ull a, ull b) {
    ull r; asm("add.rn.f32x2 %0,%1,%2;" : "=l"(r) : "l"(a), "l"(b)); return r;
}
__device__ __forceinline__ ull mul2(ull a, ull b) {
    ull r; asm("mul.rn.f32x2 %0,%1,%2;" : "=l"(r) : "l"(a), "l"(b)); return r;
}
__device__ __forceinline__ ull fma2(ull a, ull b, ull c) {
    ull r; asm("fma.rn.f32x2 %0,%1,%2,%3;" : "=l"(r) : "l"(a), "l"(b), "l"(c)); return r;
}
__device__ __forceinline__ ull min2(ull a, ull b) {
    float al, ah, bl, bh; upk2(a, al, ah); upk2(b, bl, bh);
    return pk2(fminf(al, bl), fminf(ah, bh));
}
__device__ __forceinline__ ull max2(ull a, ull b) {
    float al, ah, bl, bh; upk2(a, al, ah); upk2(b, bl, bh);
    return pk2(fmaxf(al, bl), fmaxf(ah, bh));
}

__device__ __forceinline__ int ld_acq(const int* p) {
    int v; asm volatile("ld.acquire.gpu.global.b32 %0,[%1];" : "=r"(v) : "l"(p)); return v;
}
__device__ __forceinline__ void st_rel(int* p, int v) {
    asm volatile("st.release.gpu.global.b32 [%0],%1;" :: "l"(p), "r"(v) : "memory");
}

#define GBAR(id) asm volatile("bar.sync %0,%1;" :: "r"(id), "r"(128) : "memory")

__global__ void reset_kernel() {
    if (threadIdx.x < BB) g_prog[threadIdx.x * 32] = -1;
}

// ---------------------------------------------------------------------------
// Fused kernel. CTAs 0..7: FPS producer (R7-identical math + progress stores).
// CTAs 8..147: workers, 8 groups of 128 threads; each group: low-pressure
// backoff spin on progress, ball-query (warp0, smem), gather, FFMA2 MLP.
// ---------------------------------------------------------------------------
__global__ __launch_bounds__(1024, 1)
void fused_kernel(const float* __restrict__ xyz, const float* __restrict__ feat,
                  const float* __restrict__ w1, const float* __restrict__ b1,
                  const float* __restrict__ w2, const float* __restrict__ b2,
                  const float* __restrict__ w3, const float* __restrict__ b3,
                  float* __restrict__ newxyz, float* __restrict__ outf) {
    extern __shared__ float smdyn[];
    __shared__ unsigned swmax[2][32];
    __shared__ int swidx[2];
    __shared__ int sidx[8][KK];

    int tid = threadIdx.x;

    if (blockIdx.x < BB) {
        // ================= FPS producer =================
        int b = blockIdx.x;
        const float* x = xyz + (long)b * NN * 3;
        int lane = tid & 31;
        int wid = tid >> 5;

        ull pxp[4], pyp[4], pzp[4], ddp[4];
#pragma unroll
        for (int jp = 0; jp < 4; jp++) {
            int p0 = (2 * jp) * 1024 + tid;
            int p1 = (2 * jp + 1) * 1024 + tid;
            pxp[jp] = pk2(x[p0 * 3 + 0], x[p1 * 3 + 0]);
            pyp[jp] = pk2(x[p0 * 3 + 1], x[p1 * 3 + 1]);
            pzp[jp] = pk2(x[p0 * 3 + 2], x[p1 * 3 + 2]);
            ddp[jp] = pk2(1e10f, 1e10f);
        }

        if (tid == 0) { swidx[0] = 0x7fffffff; swidx[1] = 0x7fffffff; }

        float lx = __ldg(x + 0), ly = __ldg(x + 1), lz = __ldg(x + 2);
        if (tid == 0) {
            newxyz[(long)b * MM * 3 + 0] = lx;
            newxyz[(long)b * MM * 3 + 1] = ly;
            newxyz[(long)b * MM * 3 + 2] = lz;
            st_rel(&g_prog[b * 32], 0);
        }
        __syncthreads();

        for (int it = 1; it < MM; it++) {
            int buf = it & 1;
            ull nlx = pk2(-lx, -lx), nly = pk2(-ly, -ly), nlz = pk2(-lz, -lz);
#pragma unroll
            for (int jp = 0; jp < 4; jp++) {
                ull dx = add2(pxp[jp], nlx);
                ull dy = add2(pyp[jp], nly);
                ull dz = add2(pzp[jp], nlz);
                ull m = mul2(dz, dz);
                m = fma2(dy, dy, m);
                m = fma2(dx, dx, m);
                ddp[jp] = min2(ddp[jp], m);
            }
            ull t01 = max2(ddp[0], ddp[1]);
            ull t23 = max2(ddp[2], ddp[3]);
            ull tm = max2(t01, t23);
            float m0, m1;
            upk2(tm, m0, m1);
            unsigned bdu = __float_as_uint(fmaxf(m0, m1));

            unsigned wm = __reduce_max_sync(0xffffffffu, bdu);
            if (lane == 0) swmax[buf][wid] = wm;
            __syncthreads();

            unsigned gb = __reduce_max_sync(0xffffffffu, swmax[buf][lane]);

            if (bdu == gb) {
                int bj = 0;
#pragma unroll
                for (int jp = 3; jp >= 0; jp--) {
                    float lo, hi;
                    upk2(ddp[jp], lo, hi);
                    if (__float_as_uint(hi) == gb) bj = 2 * jp + 1;
                    if (__float_as_uint(lo) == gb) bj = 2 * jp;
                }
                atomicMin(&swidx[buf], bj * 1024 + tid);
            }
            __syncthreads();

            int w = swidx[buf];
            if (tid == 0) swidx[buf ^ 1] = 0x7fffffff;

            lx = __ldg(x + w * 3 + 0);
            ly = __ldg(x + w * 3 + 1);
            lz = __ldg(x + w * 3 + 2);
            if (tid == 0) {
                newxyz[(long)b * MM * 3 + it * 3 + 0] = lx;
                newxyz[(long)b * MM * 3 + it * 3 + 1] = ly;
                newxyz[(long)b * MM * 3 + it * 3 + 2] = lz;
                st_rel(&g_prog[b * 32], it);
            }
        }
        return;
    }

    // ================= workers =================
    float* sw1 = smdyn;              // [67][64]
    float* sw2 = sw1 + CIN * 64;     // [64][64]
    float* sw3 = sw2 + 64 * 64;      // [64][128]
    float* sb1 = sw3 + 64 * 128;     // 64
    float* sb2 = sb1 + 64;           // 64
    float* sb3 = sb2 + 64;           // 128
    float* bufs = sb3 + 128;         // 8 * (67*32 + 64*32)

    for (int i = tid; i < 64 * CIN; i += 1024) sw1[(i % CIN) * 64 + (i / CIN)] = w1[i];
    for (int i = tid; i < 64 * 64; i += 1024) sw2[(i & 63) * 64 + (i >> 6)] = w2[i];
    for (int i = tid; i < 128 * 64; i += 1024) sw3[(i & 63) * 128 + (i >> 6)] = w3[i];
    if (tid < 64) { sb1[tid] = b1[tid]; sb2[tid] = b2[tid]; }
    if (tid < 128) sb3[tid] = b3[tid];
    __syncthreads();

    int group = tid >> 7;
    int gtid = tid & 127;
    int lane = tid & 31;
    int gw = gtid >> 5;
    float* xin = bufs + group * (CIN * 32 + 64 * 32);
    float* h1 = xin + CIN * 32;
    int* sid = sidx[group];

    int s = gtid >> 2, part = gtid & 3;   // gather mapping
    int sg = gtid & 7, og = gtid >> 3;    // compute mapping
    int s0 = sg * 4;
    int barid = group + 1;

    int nG = (gridDim.x - BB) * 8;
    for (int idx = (blockIdx.x - BB) * 8 + group; idx < BB * MM; idx += nG) {
        int m = idx >> 3, b = idx & 7;

        // ---- wait for producer (lane 0, gap-aware backoff) + ball query ----
        if (gw == 0) {
            if (lane == 0) {
                const int* gp = &g_prog[b * 32];
                int p = ld_acq(gp);
                unsigned ns = 256;
                while (p < m) {
                    int gap = m - p;
                    __nanosleep(gap >= 8 ? 1024u : ns);
                    if (ns < 4096) ns <<= 1;
                    p = ld_acq(gp);
                }
            }
            __syncwarp();
            const float* x = xyz + (long)b * NN * 3;
            const float* nx = newxyz + ((long)b * MM + m) * 3;
            float cx = nx[0], cy = nx[1], cz = nx[2];
            int cnt = 0, first = 0;
            bool hf = false;
            for (int ch = 0; ch < NN / 32 && cnt < KK; ch++) {
                int p = ch * 32 + lane;
                float dx = x[p * 3 + 0] - cx;
                float dy = x[p * 3 + 1] - cy;
                float dz = x[p * 3 + 2] - cz;
                float d2 = fmaf(dx, dx, fmaf(dy, dy, dz * dz));
                bool in = d2 < R2;
                unsigned mk = __ballot_sync(0xffffffffu, in);
                if (mk) {
                    if (!hf) { first = ch * 32 + __ffs(mk) - 1; hf = true; }
                    if (in) {
                        int pos = cnt + __popc(mk & ((1u << lane) - 1u));
                        if (pos < KK) sid[pos] = p;
                    }
                    cnt += __popc(mk);
                }
            }
            for (int i2 = cnt + lane; i2 < KK; i2 += 32) sid[i2] = first;
        }
        GBAR(barid);

        // ---- gather ----
        {
            const float* nx = newxyz + ((long)b * MM + m) * 3;
            float cx = nx[0], cy = nx[1], cz = nx[2];
            int pi = sid[s];
            const float4* frow = (const float4*)(feat + ((long)b * NN + pi) * CC) + part * 4;
#pragma unroll
            for (int q = 0; q < 4; q++) {
                float4 v = frow[q];
                int c0 = 3 + part * 16 + q * 4;
                xin[(c0 + 0) * 32 + s] = v.x;
                xin[(c0 + 1) * 32 + s] = v.y;
                xin[(c0 + 2) * 32 + s] = v.z;
                xin[(c0 + 3) * 32 + s] = v.w;
            }
            if (part == 0) {
                const float* pr = xyz + ((long)b * NN + pi) * 3;
                xin[0 * 32 + s] = pr[0] - cx;
                xin[1 * 32 + s] = pr[1] - cy;
                xin[2 * 32 + s] = pr[2] - cz;
            }
        }
        GBAR(barid);

        // ---- layer 1: 67 -> 64 ----
        {
            int o0 = og * 4;
            ull acc[4][2];
#pragma unroll
            for (int i = 0; i < 4; i++) { acc[i][0] = 0ull; acc[i][1] = 0ull; }
            for (int c = 0; c < CIN; c++) {
                float4 xv = *(const float4*)&xin[c * 32 + s0];
                ulonglong2 wv = *(const ulonglong2*)&sw1[c * 64 + o0];
                ull xb[4] = {pk2(xv.x, xv.x), pk2(xv.y, xv.y), pk2(xv.z, xv.z), pk2(xv.w, xv.w)};
#pragma unroll
                for (int i = 0; i < 4; i++) {
                    acc[i][0] = fma2(xb[i], wv.x, acc[i][0]);
                    acc[i][1] = fma2(xb[i], wv.y, acc[i][1]);
                }
            }
            ull bp0 = *(const ull*)&sb1[o0];
            ull bp1 = *(const ull*)&sb1[o0 + 2];
            float f[4][4];
#pragma unroll
            for (int i = 0; i < 4; i++) {
                upk2(max2(add2(acc[i][0], bp0), 0ull), f[i][0], f[i][1]);
                upk2(max2(add2(acc[i][1], bp1), 0ull), f[i][2], f[i][3]);
            }
#pragma unroll
            for (int j = 0; j < 4; j++)
                *(float4*)&h1[(o0 + j) * 32 + s0] =
                    make_float4(f[0][j], f[1][j], f[2][j], f[3][j]);
        }
        GBAR(barid);

        // ---- layer 2: 64 -> 64 ----
        {
            int o0 = og * 4;
            ull acc[4][2];
#pragma unroll
            for (int i = 0; i < 4; i++) { acc[i][0] = 0ull; acc[i][1] = 0ull; }
            for (int c = 0; c < 64; c++) {
                float4 xv = *(const float4*)&h1[c * 32 + s0];
                ulonglong2 wv = *(const ulonglong2*)&sw2[c * 64 + o0];
                ull xb[4] = {pk2(xv.x, xv.x), pk2(xv.y, xv.y), pk2(xv.z, xv.z), pk2(xv.w, xv.w)};
#pragma unroll
                for (int i = 0; i < 4; i++) {
                    acc[i][0] = fma2(xb[i], wv.x, acc[i][0]);
                    acc[i][1] = fma2(xb[i], wv.y, acc[i][1]);
                }
            }
            ull bp0 = *(const ull*)&sb2[o0];
            ull bp1 = *(const ull*)&sb2[o0 + 2];
            float f[4][4];
#pragma unroll
            for (int i = 0; i < 4; i++) {
                upk2(max2(add2(acc[i][0], bp0), 0ull), f[i][0], f[i][1]);
                upk2(max2(add2(acc[i][1], bp1), 0ull), f[i][2], f[i][3]);
            }
#pragma unroll
            for (int j = 0; j < 4; j++)
                *(float4*)&xin[(o0 + j) * 32 + s0] =
                    make_float4(f[0][j], f[1][j], f[2][j], f[3][j]);
        }
        GBAR(barid);

        // ---- layer 3: 64 -> 128, two 4x4 halves, maxpool ----
        float* op = outf + (long)b * 128 * 1024 + m;
#pragma unroll
        for (int half = 0; half < 2; half++) {
            int oo = og * 8 + half * 4;
            ull a3[4][2];
#pragma unroll
            for (int i = 0; i < 4; i++) { a3[i][0] = 0ull; a3[i][1] = 0ull; }
            for (int c = 0; c < 64; c++) {
                float4 xv = *(const float4*)&xin[c * 32 + s0];
                ulonglong2 wa = *(const ulonglong2*)&sw3[c * 128 + oo];
                ull xb[4] = {pk2(xv.x, xv.x), pk2(xv.y, xv.y), pk2(xv.z, xv.z), pk2(xv.w, xv.w)};
#pragma unroll
                for (int i = 0; i < 4; i++) {
                    a3[i][0] = fma2(xb[i], wa.x, a3[i][0]);
                    a3[i][1] = fma2(xb[i], wa.y, a3[i][1]);
                }
            }
            ull mx[2];
#pragma unroll
            for (int q = 0; q < 2; q++) {
                ull bp = *(const ull*)&sb3[oo + 2 * q];
                ull v = max2(add2(a3[0][q], bp), 0ull);
                v = max2(v, max2(add2(a3[1][q], bp), 0ull));
                v = max2(v, max2(add2(a3[2][q], bp), 0ull));
                v = max2(v, max2(add2(a3[3][q], bp), 0ull));
                mx[q] = v;
            }
#pragma unroll
            for (int off = 1; off < 8; off <<= 1) {
#pragma unroll
                for (int q = 0; q < 2; q++) {
                    ull o = __shfl_xor_sync(0xffffffffu, mx[q], off);
                    mx[q] = max2(mx[q], o);
                }
            }
            if (sg == 0) {
#pragma unroll
                for (int q = 0; q < 2; q++) {
                    float v0, v1;
                    upk2(mx[q], v0, v1);
                    op[(long)(oo + 2 * q) * 1024] = v0;
                    op[(long)(oo + 2 * q + 1) * 1024] = v1;
                }
            }
        }
        GBAR(barid);
    }
}

// ---------------------------------------------------------------------------
extern "C" void kernel_launch(void* const* d_in, const int* in_sizes, int n_in,
                              void* d_out, int out_size) {
    const float* xyz = (const float*)d_in[0];
    const float* feat = (const float*)d_in[1];
    const float* w1 = (const float*)d_in[2];
    const float* b1 = (const float*)d_in[3];
    const float* w2 = (const float*)d_in[4];
    const float* b2 = (const float*)d_in[5];
    const float* w3 = (const float*)d_in[6];
    const float* b3 = (const float*)d_in[7];
    float* out = (float*)d_out;
    float* newxyz = out;                       // (B, M, 3)
    float* outf = out + (long)BB * MM * 3;     // (B, 128, M)

    reset_kernel<<<1, 32>>>();

    int smem = (CIN * 64 + 64 * 64 + 64 * 128 + 64 + 64 + 128 +
                8 * (CIN * 32 + 64 * 32)) * 4;   // 201472 bytes
    cudaFuncSetAttribute(fused_kernel, cudaFuncAttributeMaxDynamicSharedMemorySize, smem);
    fused_kernel<<<148, 1024, smem>>>(xyz, feat, w1, b1, w2, b2, w3, b3, newxyz, outf);

    (void)in_sizes; (void)n_in; (void)out_size;
}

// round 13
// speedup vs baseline: 1.0580x; 1.0580x over previous
#include <cuda_runtime.h>

#define BB 8
#define NN 8192
#define MM 1024
#define KK 32
#define CC 64
#define CIN 67
#define R2 0.16f

typedef unsigned long long ull;

// one counter per 128B line
__device__ int g_prog[BB * 32];

// ---- packed f32x2 helpers (sm_100+: only add/mul/fma exist packed) ----
__device__ __forceinline__ ull pk2(float a, float b) {
    ull r; asm("mov.b64 %0,{%1,%2};" : "=l"(r) : "f"(a), "f"(b)); return r;
}
__device__ __forceinline__ void upk2(ull v, float& a, float& b) {
    asm("mov.b64 {%0,%1},%2;" : "=f"(a), "=f"(b) : "l"(v));
}
__device__ __forceinline__ ull add2(ull a, ull b) {
    ull r; asm("add.rn.f32x2 %0,%1,%2;" : "=l"(r) : "l"(a), "l"(b)); return r;
}
__device__ __forceinline__ ull mul2(ull a, ull b) {
    ull r; asm("mul.rn.f32x2 %0,%1,%2;" : "=l"(r) : "l"(a), "l"(b)); return r;
}
__device__ __forceinline__ ull fma2(ull a, ull b, ull c) {
    ull r; asm("fma.rn.f32x2 %0,%1,%2,%3;" : "=l"(r) : "l"(a), "l"(b), "l"(c)); return r;
}
__device__ __forceinline__ ull min2(ull a, ull b) {
    float al, ah, bl, bh; upk2(a, al, ah); upk2(b, bl, bh);
    return pk2(fminf(al, bl), fminf(ah, bh));
}
__device__ __forceinline__ ull max2(ull a, ull b) {
    float al, ah, bl, bh; upk2(a, al, ah); upk2(b, bl, bh);
    return pk2(fmaxf(al, bl), fmaxf(ah, bh));
}

__device__ __forceinline__ int ld_acq(const int* p) {
    int v; asm volatile("ld.acquire.gpu.global.b32 %0,[%1];" : "=r"(v) : "l"(p)); return v;
}
__device__ __forceinline__ void st_rel(int* p, int v) {
    asm volatile("st.release.gpu.global.b32 [%0],%1;" :: "l"(p), "r"(v) : "memory");
}

#define GBAR(id) asm volatile("bar.sync %0,%1;" :: "r"(id), "r"(128) : "memory")

__global__ void reset_kernel() {
    if (threadIdx.x < BB) g_prog[threadIdx.x * 32] = -1;
}

// ---------------------------------------------------------------------------
// Fused kernel. CTAs 0..7: FPS producer with xyz resident in the CTA's
// (otherwise unused) 201KB dynamic smem -> winner-coord fetch is a 29cyc
// broadcast LDS instead of an L2-latency LDG on the serial chain.
// CTAs 8..147: workers (unchanged).
// ---------------------------------------------------------------------------
__global__ __launch_bounds__(1024, 1)
void fused_kernel(const float* __restrict__ xyz, const float* __restrict__ feat,
                  const float* __restrict__ w1, const float* __restrict__ b1,
                  const float* __restrict__ w2, const float* __restrict__ b2,
                  const float* __restrict__ w3, const float* __restrict__ b3,
                  float* __restrict__ newxyz, float* __restrict__ outf) {
    extern __shared__ float smdyn[];
    __shared__ unsigned swmax[2][32];
    __shared__ int swidx[2];
    __shared__ int sidx[8][KK];

    int tid = threadIdx.x;

    if (blockIdx.x < BB) {
        // ================= FPS producer =================
        int b = blockIdx.x;
        const float* x = xyz + (long)b * NN * 3;
        int lane = tid & 31;
        int wid = tid >> 5;
        float* sxyz = smdyn;   // [NN*3] = 96KB, lives in this CTA's 201KB carveout

        // stage xyz into smem (coalesced, once)
        for (int i = tid; i < NN * 3; i += 1024) sxyz[i] = x[i];

        ull pxp[4], pyp[4], pzp[4], ddp[4];
#pragma unroll
        for (int jp = 0; jp < 4; jp++) {
            int p0 = (2 * jp) * 1024 + tid;
            int p1 = (2 * jp + 1) * 1024 + tid;
            pxp[jp] = pk2(x[p0 * 3 + 0], x[p1 * 3 + 0]);
            pyp[jp] = pk2(x[p0 * 3 + 1], x[p1 * 3 + 1]);
            pzp[jp] = pk2(x[p0 * 3 + 2], x[p1 * 3 + 2]);
            ddp[jp] = pk2(1e10f, 1e10f);
        }

        if (tid == 0) { swidx[0] = 0x7fffffff; swidx[1] = 0x7fffffff; }

        float lx = __ldg(x + 0), ly = __ldg(x + 1), lz = __ldg(x + 2);
        if (tid == 0) {
            newxyz[(long)b * MM * 3 + 0] = lx;
            newxyz[(long)b * MM * 3 + 1] = ly;
            newxyz[(long)b * MM * 3 + 2] = lz;
            st_rel(&g_prog[b * 32], 0);
        }
        __syncthreads();

        for (int it = 1; it < MM; it++) {
            int buf = it & 1;
            ull nlx = pk2(-lx, -lx), nly = pk2(-ly, -ly), nlz = pk2(-lz, -lz);
#pragma unroll
            for (int jp = 0; jp < 4; jp++) {
                ull dx = add2(pxp[jp], nlx);
                ull dy = add2(pyp[jp], nly);
                ull dz = add2(pzp[jp], nlz);
                ull m = mul2(dz, dz);
                m = fma2(dy, dy, m);
                m = fma2(dx, dx, m);
                ddp[jp] = min2(ddp[jp], m);
            }
            ull t01 = max2(ddp[0], ddp[1]);
            ull t23 = max2(ddp[2], ddp[3]);
            ull tm = max2(t01, t23);
            float m0, m1;
            upk2(tm, m0, m1);
            unsigned bdu = __float_as_uint(fmaxf(m0, m1));

            unsigned wm = __reduce_max_sync(0xffffffffu, bdu);
            if (lane == 0) swmax[buf][wid] = wm;
            __syncthreads();

            unsigned gb = __reduce_max_sync(0xffffffffu, swmax[buf][lane]);

            if (bdu == gb) {
                int bj = 0;
#pragma unroll
                for (int jp = 3; jp >= 0; jp--) {
                    float lo, hi;
                    upk2(ddp[jp], lo, hi);
                    if (__float_as_uint(hi) == gb) bj = 2 * jp + 1;
                    if (__float_as_uint(lo) == gb) bj = 2 * jp;
                }
                atomicMin(&swidx[buf], bj * 1024 + tid);
            }
            __syncthreads();

            int w = swidx[buf];
            if (tid == 0) swidx[buf ^ 1] = 0x7fffffff;

            // broadcast LDS (29cyc) -- no gmem on the serial chain
            lx = sxyz[w * 3 + 0];
            ly = sxyz[w * 3 + 1];
            lz = sxyz[w * 3 + 2];
            if (tid == 0) {
                newxyz[(long)b * MM * 3 + it * 3 + 0] = lx;
                newxyz[(long)b * MM * 3 + it * 3 + 1] = ly;
                newxyz[(long)b * MM * 3 + it * 3 + 2] = lz;
                st_rel(&g_prog[b * 32], it);
            }
        }
        return;
    }

    // ================= workers =================
    float* sw1 = smdyn;              // [67][64]
    float* sw2 = sw1 + CIN * 64;     // [64][64]
    float* sw3 = sw2 + 64 * 64;      // [64][128]
    float* sb1 = sw3 + 64 * 128;     // 64
    float* sb2 = sb1 + 64;           // 64
    float* sb3 = sb2 + 64;           // 128
    float* bufs = sb3 + 128;         // 8 * (67*32 + 64*32)

    for (int i = tid; i < 64 * CIN; i += 1024) sw1[(i % CIN) * 64 + (i / CIN)] = w1[i];
    for (int i = tid; i < 64 * 64; i += 1024) sw2[(i & 63) * 64 + (i >> 6)] = w2[i];
    for (int i = tid; i < 128 * 64; i += 1024) sw3[(i & 63) * 128 + (i >> 6)] = w3[i];
    if (tid < 64) { sb1[tid] = b1[tid]; sb2[tid] = b2[tid]; }
    if (tid < 128) sb3[tid] = b3[tid];
    __syncthreads();

    int group = tid >> 7;
    int gtid = tid & 127;
    int lane = tid & 31;
    int gw = gtid >> 5;
    float* xin = bufs + group * (CIN * 32 + 64 * 32);
    float* h1 = xin + CIN * 32;
    int* sid = sidx[group];

    int s = gtid >> 2, part = gtid & 3;   // gather mapping
    int sg = gtid & 7, og = gtid >> 3;    // compute mapping
    int s0 = sg * 4;
    int barid = group + 1;

    int nG = (gridDim.x - BB) * 8;
    for (int idx = (blockIdx.x - BB) * 8 + group; idx < BB * MM; idx += nG) {
        int m = idx >> 3, b = idx & 7;

        // ---- wait for producer (lane 0, backoff) + ball query ----
        if (gw == 0) {
            if (lane == 0) {
                const int* gp = &g_prog[b * 32];
                int p = ld_acq(gp);
                unsigned ns = 256;
                while (p < m) {
                    int gap = m - p;
                    __nanosleep(gap >= 8 ? 1024u : ns);
                    if (ns < 4096) ns <<= 1;
                    p = ld_acq(gp);
                }
            }
            __syncwarp();
            const float* x = xyz + (long)b * NN * 3;
            const float* nx = newxyz + ((long)b * MM + m) * 3;
            float cx = nx[0], cy = nx[1], cz = nx[2];
            int cnt = 0, first = 0;
            bool hf = false;
            for (int ch = 0; ch < NN / 32 && cnt < KK; ch++) {
                int p = ch * 32 + lane;
                float dx = x[p * 3 + 0] - cx;
                float dy = x[p * 3 + 1] - cy;
                float dz = x[p * 3 + 2] - cz;
                float d2 = fmaf(dx, dx, fmaf(dy, dy, dz * dz));
                bool in = d2 < R2;
                unsigned mk = __ballot_sync(0xffffffffu, in);
                if (mk) {
                    if (!hf) { first = ch * 32 + __ffs(mk) - 1; hf = true; }
                    if (in) {
                        int pos = cnt + __popc(mk & ((1u << lane) - 1u));
                        if (pos < KK) sid[pos] = p;
                    }
                    cnt += __popc(mk);
                }
            }
            for (int i2 = cnt + lane; i2 < KK; i2 += 32) sid[i2] = first;
        }
        GBAR(barid);

        // ---- gather ----
        {
            const float* nx = newxyz + ((long)b * MM + m) * 3;
            float cx = nx[0], cy = nx[1], cz = nx[2];
            int pi = sid[s];
            const float4* frow = (const float4*)(feat + ((long)b * NN + pi) * CC) + part * 4;
#pragma unroll
            for (int q = 0; q < 4; q++) {
                float4 v = frow[q];
                int c0 = 3 + part * 16 + q * 4;
                xin[(c0 + 0) * 32 + s] = v.x;
                xin[(c0 + 1) * 32 + s] = v.y;
                xin[(c0 + 2) * 32 + s] = v.z;
                xin[(c0 + 3) * 32 + s] = v.w;
            }
            if (part == 0) {
                const float* pr = xyz + ((long)b * NN + pi) * 3;
                xin[0 * 32 + s] = pr[0] - cx;
                xin[1 * 32 + s] = pr[1] - cy;
                xin[2 * 32 + s] = pr[2] - cz;
            }
        }
        GBAR(barid);

        // ---- layer 1: 67 -> 64 ----
        {
            int o0 = og * 4;
            ull acc[4][2];
#pragma unroll
            for (int i = 0; i < 4; i++) { acc[i][0] = 0ull; acc[i][1] = 0ull; }
            for (int c = 0; c < CIN; c++) {
                float4 xv = *(const float4*)&xin[c * 32 + s0];
                ulonglong2 wv = *(const ulonglong2*)&sw1[c * 64 + o0];
                ull xb[4] = {pk2(xv.x, xv.x), pk2(xv.y, xv.y), pk2(xv.z, xv.z), pk2(xv.w, xv.w)};
#pragma unroll
                for (int i = 0; i < 4; i++) {
                    acc[i][0] = fma2(xb[i], wv.x, acc[i][0]);
                    acc[i][1] = fma2(xb[i], wv.y, acc[i][1]);
                }
            }
            ull bp0 = *(const ull*)&sb1[o0];
            ull bp1 = *(const ull*)&sb1[o0 + 2];
            float f[4][4];
#pragma unroll
            for (int i = 0; i < 4; i++) {
                upk2(max2(add2(acc[i][0], bp0), 0ull), f[i][0], f[i][1]);
                upk2(max2(add2(acc[i][1], bp1), 0ull), f[i][2], f[i][3]);
            }
#pragma unroll
            for (int j = 0; j < 4; j++)
                *(float4*)&h1[(o0 + j) * 32 + s0] =
                    make_float4(f[0][j], f[1][j], f[2][j], f[3][j]);
        }
        GBAR(barid);

        // ---- layer 2: 64 -> 64 ----
        {
            int o0 = og * 4;
            ull acc[4][2];
#pragma unroll
            for (int i = 0; i < 4; i++) { acc[i][0] = 0ull; acc[i][1] = 0ull; }
            for (int c = 0; c < 64; c++) {
                float4 xv = *(const float4*)&h1[c * 32 + s0];
                ulonglong2 wv = *(const ulonglong2*)&sw2[c * 64 + o0];
                ull xb[4] = {pk2(xv.x, xv.x), pk2(xv.y, xv.y), pk2(xv.z, xv.z), pk2(xv.w, xv.w)};
#pragma unroll
                for (int i = 0; i < 4; i++) {
                    acc[i][0] = fma2(xb[i], wv.x, acc[i][0]);
                    acc[i][1] = fma2(xb[i], wv.y, acc[i][1]);
                }
            }
            ull bp0 = *(const ull*)&sb2[o0];
            ull bp1 = *(const ull*)&sb2[o0 + 2];
            float f[4][4];
#pragma unroll
            for (int i = 0; i < 4; i++) {
                upk2(max2(add2(acc[i][0], bp0), 0ull), f[i][0], f[i][1]);
                upk2(max2(add2(acc[i][1], bp1), 0ull), f[i][2], f[i][3]);
            }
#pragma unroll
            for (int j = 0; j < 4; j++)
                *(float4*)&xin[(o0 + j) * 32 + s0] =
                    make_float4(f[0][j], f[1][j], f[2][j], f[3][j]);
        }
        GBAR(barid);

        // ---- layer 3: 64 -> 128, two 4x4 halves, maxpool ----
        float* op = outf + (long)b * 128 * 1024 + m;
#pragma unroll
        for (int half = 0; half < 2; half++) {
            int oo = og * 8 + half * 4;
            ull a3[4][2];
#pragma unroll
            for (int i = 0; i < 4; i++) { a3[i][0] = 0ull; a3[i][1] = 0ull; }
            for (int c = 0; c < 64; c++) {
                float4 xv = *(const float4*)&xin[c * 32 + s0];
                ulonglong2 wa = *(const ulonglong2*)&sw3[c * 128 + oo];
                ull xb[4] = {pk2(xv.x, xv.x), pk2(xv.y, xv.y), pk2(xv.z, xv.z), pk2(xv.w, xv.w)};
#pragma unroll
                for (int i = 0; i < 4; i++) {
                    a3[i][0] = fma2(xb[i], wa.x, a3[i][0]);
                    a3[i][1] = fma2(xb[i], wa.y, a3[i][1]);
                }
            }
            ull mx[2];
#pragma unroll
            for (int q = 0; q < 2; q++) {
                ull bp = *(const ull*)&sb3[oo + 2 * q];
                ull v = max2(add2(a3[0][q], bp), 0ull);
                v = max2(v, max2(add2(a3[1][q], bp), 0ull));
                v = max2(v, max2(add2(a3[2][q], bp), 0ull));
                v = max2(v, max2(add2(a3[3][q], bp), 0ull));
                mx[q] = v;
            }
#pragma unroll
            for (int off = 1; off < 8; off <<= 1) {
#pragma unroll
                for (int q = 0; q < 2; q++) {
                    ull o = __shfl_xor_sync(0xffffffffu, mx[q], off);
                    mx[q] = max2(mx[q], o);
                }
            }
            if (sg == 0) {
#pragma unroll
                for (int q = 0; q < 2; q++) {
                    float v0, v1;
                    upk2(mx[q], v0, v1);
                    op[(long)(oo + 2 * q) * 1024] = v0;
                    op[(long)(oo + 2 * q + 1) * 1024] = v1;
                }
            }
        }
        GBAR(barid);
    }
}

// ---------------------------------------------------------------------------
extern "C" void kernel_launch(void* const* d_in, const int* in_sizes, int n_in,
                              void* d_out, int out_size) {
    const float* xyz = (const float*)d_in[0];
    const float* feat = (const float*)d_in[1];
    const float* w1 = (const float*)d_in[2];
    const float* b1 = (const float*)d_in[3];
    const float* w2 = (const float*)d_in[4];
    const float* b2 = (const float*)d_in[5];
    const float* w3 = (const float*)d_in[6];
    const float* b3 = (const float*)d_in[7];
    float* out = (float*)d_out;
    float* newxyz = out;                       // (B, M, 3)
    float* outf = out + (long)BB * MM * 3;     // (B, 128, M)

    reset_kernel<<<1, 32>>>();

    int smem = (CIN * 64 + 64 * 64 + 64 * 128 + 64 + 64 + 128 +
                8 * (CIN * 32 + 64 * 32)) * 4;   // 201472 bytes (>= NN*3*4 = 96KB)
    cudaFuncSetAttribute(fused_kernel, cudaFuncAttributeMaxDynamicSharedMemorySize, smem);
    fused_kernel<<<148, 1024, smem>>>(xyz, feat, w1, b1, w2, b2, w3, b3, newxyz, outf);

    (void)in_sizes; (void)n_in; (void)out_size;
}

// round 14
// speedup vs baseline: 1.3860x; 1.3100x over previous
#include <cuda_runtime.h>

#define BB 8
#define NN 8192
#define MM 1024
#define KK 32
#define CC 64
#define CIN 67
#define R2 0.16f

typedef unsigned long long ull;

// one counter per 128B line
__device__ int g_prog[BB * 32];

// ---- packed f32x2 helpers (sm_100+: only add/mul/fma exist packed) ----
__device__ __forceinline__ ull pk2(float a, float b) {
    ull r; asm("mov.b64 %0,{%1,%2};" : "=l"(r) : "f"(a), "f"(b)); return r;
}
__device__ __forceinline__ void upk2(ull v, float& a, float& b) {
    asm("mov.b64 {%0,%1},%2;" : "=f"(a), "=f"(b) : "l"(v));
}
__device__ __forceinline__ ull add2(ull a, ull b) {
    ull r; asm("add.rn.f32x2 %0,%1,%2;" : "=l"(r) : "l"(a), "l"(b)); return r;
}
__device__ __forceinline__ ull mul2(ull a, ull b) {
    ull r; asm("mul.rn.f32x2 %0,%1,%2;" : "=l"(r) : "l"(a), "l"(b)); return r;
}
__device__ __forceinline__ ull fma2(ull a, ull b, ull c) {
    ull r; asm("fma.rn.f32x2 %0,%1,%2,%3;" : "=l"(r) : "l"(a), "l"(b), "l"(c)); return r;
}
__device__ __forceinline__ ull min2(ull a, ull b) {
    float al, ah, bl, bh; upk2(a, al, ah); upk2(b, bl, bh);
    return pk2(fminf(al, bl), fminf(ah, bh));
}
__device__ __forceinline__ ull max2(ull a, ull b) {
    float al, ah, bl, bh; upk2(a, al, ah); upk2(b, bl, bh);
    return pk2(fmaxf(al, bl), fmaxf(ah, bh));
}

__device__ __forceinline__ int ld_acq(const int* p) {
    int v; asm volatile("ld.acquire.gpu.global.b32 %0,[%1];" : "=r"(v) : "l"(p)); return v;
}
__device__ __forceinline__ void st_rel(int* p, int v) {
    asm volatile("st.release.gpu.global.b32 [%0],%1;" :: "l"(p), "r"(v) : "memory");
}

#define GBAR(id) asm volatile("bar.sync %0,%1;" :: "r"(id), "r"(128) : "memory")

__global__ void reset_kernel() {
    if (threadIdx.x < BB) g_prog[threadIdx.x * 32] = -1;
}

// ---------------------------------------------------------------------------
// Fused kernel. CTAs 0..7: FPS producer, xyz in smem, progress published
// (st.release.gpu = MEMBAR.GPU) only every 16 iterations to keep the fence
// off the per-iteration serial chain. CTAs 8..147: workers.
// ---------------------------------------------------------------------------
__global__ __launch_bounds__(1024, 1)
void fused_kernel(const float* __restrict__ xyz, const float* __restrict__ feat,
                  const float* __restrict__ w1, const float* __restrict__ b1,
                  const float* __restrict__ w2, const float* __restrict__ b2,
                  const float* __restrict__ w3, const float* __restrict__ b3,
                  float* __restrict__ newxyz, float* __restrict__ outf) {
    extern __shared__ float smdyn[];
    __shared__ unsigned swmax[2][32];
    __shared__ int swidx[2];
    __shared__ int sidx[8][KK];

    int tid = threadIdx.x;

    if (blockIdx.x < BB) {
        // ================= FPS producer =================
        int b = blockIdx.x;
        const float* x = xyz + (long)b * NN * 3;
        int lane = tid & 31;
        int wid = tid >> 5;
        float* sxyz = smdyn;   // [NN*3] = 96KB in this CTA's carveout

        for (int i = tid; i < NN * 3; i += 1024) sxyz[i] = x[i];

        ull pxp[4], pyp[4], pzp[4], ddp[4];
#pragma unroll
        for (int jp = 0; jp < 4; jp++) {
            int p0 = (2 * jp) * 1024 + tid;
            int p1 = (2 * jp + 1) * 1024 + tid;
            pxp[jp] = pk2(x[p0 * 3 + 0], x[p1 * 3 + 0]);
            pyp[jp] = pk2(x[p0 * 3 + 1], x[p1 * 3 + 1]);
            pzp[jp] = pk2(x[p0 * 3 + 2], x[p1 * 3 + 2]);
            ddp[jp] = pk2(1e10f, 1e10f);
        }

        if (tid == 0) { swidx[0] = 0x7fffffff; swidx[1] = 0x7fffffff; }

        float lx = __ldg(x + 0), ly = __ldg(x + 1), lz = __ldg(x + 2);
        if (tid == 0) {
            newxyz[(long)b * MM * 3 + 0] = lx;
            newxyz[(long)b * MM * 3 + 1] = ly;
            newxyz[(long)b * MM * 3 + 2] = lz;
        }
        __syncthreads();

        for (int it = 1; it < MM; it++) {
            int buf = it & 1;
            ull nlx = pk2(-lx, -lx), nly = pk2(-ly, -ly), nlz = pk2(-lz, -lz);
#pragma unroll
            for (int jp = 0; jp < 4; jp++) {
                ull dx = add2(pxp[jp], nlx);
                ull dy = add2(pyp[jp], nly);
                ull dz = add2(pzp[jp], nlz);
                ull m = mul2(dz, dz);
                m = fma2(dy, dy, m);
                m = fma2(dx, dx, m);
                ddp[jp] = min2(ddp[jp], m);
            }
            ull t01 = max2(ddp[0], ddp[1]);
            ull t23 = max2(ddp[2], ddp[3]);
            ull tm = max2(t01, t23);
            float m0, m1;
            upk2(tm, m0, m1);
            unsigned bdu = __float_as_uint(fmaxf(m0, m1));

            unsigned wm = __reduce_max_sync(0xffffffffu, bdu);
            if (lane == 0) swmax[buf][wid] = wm;
            __syncthreads();

            unsigned gb = __reduce_max_sync(0xffffffffu, swmax[buf][lane]);

            if (bdu == gb) {
                int bj = 0;
#pragma unroll
                for (int jp = 3; jp >= 0; jp--) {
                    float lo, hi;
                    upk2(ddp[jp], lo, hi);
                    if (__float_as_uint(hi) == gb) bj = 2 * jp + 1;
                    if (__float_as_uint(lo) == gb) bj = 2 * jp;
                }
                atomicMin(&swidx[buf], bj * 1024 + tid);
            }
            __syncthreads();

            int w = swidx[buf];
            if (tid == 0) swidx[buf ^ 1] = 0x7fffffff;

            // broadcast LDS -- no gmem on the serial chain
            lx = sxyz[w * 3 + 0];
            ly = sxyz[w * 3 + 1];
            lz = sxyz[w * 3 + 2];
            if (tid == 0) {
                newxyz[(long)b * MM * 3 + it * 3 + 0] = lx;
                newxyz[(long)b * MM * 3 + it * 3 + 1] = ly;
                newxyz[(long)b * MM * 3 + it * 3 + 2] = lz;
                // amortized publish: MEMBAR.GPU only every 16 iterations
                if ((it & 15) == 15) st_rel(&g_prog[b * 32], it);
            }
        }
        return;
    }

    // ================= workers =================
    float* sw1 = smdyn;              // [67][64]
    float* sw2 = sw1 + CIN * 64;     // [64][64]
    float* sw3 = sw2 + 64 * 64;      // [64][128]
    float* sb1 = sw3 + 64 * 128;     // 64
    float* sb2 = sb1 + 64;           // 64
    float* sb3 = sb2 + 64;           // 128
    float* bufs = sb3 + 128;         // 8 * (67*32 + 64*32)

    for (int i = tid; i < 64 * CIN; i += 1024) sw1[(i % CIN) * 64 + (i / CIN)] = w1[i];
    for (int i = tid; i < 64 * 64; i += 1024) sw2[(i & 63) * 64 + (i >> 6)] = w2[i];
    for (int i = tid; i < 128 * 64; i += 1024) sw3[(i & 63) * 128 + (i >> 6)] = w3[i];
    if (tid < 64) { sb1[tid] = b1[tid]; sb2[tid] = b2[tid]; }
    if (tid < 128) sb3[tid] = b3[tid];
    __syncthreads();

    int group = tid >> 7;
    int gtid = tid & 127;
    int lane = tid & 31;
    int gw = gtid >> 5;
    float* xin = bufs + group * (CIN * 32 + 64 * 32);
    float* h1 = xin + CIN * 32;
    int* sid = sidx[group];

    int s = gtid >> 2, part = gtid & 3;   // gather mapping
    int sg = gtid & 7, og = gtid >> 3;    // compute mapping
    int s0 = sg * 4;
    int barid = group + 1;

    int nG = (gridDim.x - BB) * 8;
    for (int idx = (blockIdx.x - BB) * 8 + group; idx < BB * MM; idx += nG) {
        int m = idx >> 3, b = idx & 7;

        // ---- wait for producer (lane 0, backoff) + ball query ----
        if (gw == 0) {
            if (lane == 0) {
                const int* gp = &g_prog[b * 32];
                int p = ld_acq(gp);
                unsigned ns = 256;
                while (p < m) {
                    int gap = m - p;
                    __nanosleep(gap >= 24 ? 1024u : ns);
                    if (ns < 4096) ns <<= 1;
                    p = ld_acq(gp);
                }
            }
            __syncwarp();
            const float* x = xyz + (long)b * NN * 3;
            const float* nx = newxyz + ((long)b * MM + m) * 3;
            float cx = nx[0], cy = nx[1], cz = nx[2];
            int cnt = 0, first = 0;
            bool hf = false;
            for (int ch = 0; ch < NN / 32 && cnt < KK; ch++) {
                int p = ch * 32 + lane;
                float dx = x[p * 3 + 0] - cx;
                float dy = x[p * 3 + 1] - cy;
                float dz = x[p * 3 + 2] - cz;
                float d2 = fmaf(dx, dx, fmaf(dy, dy, dz * dz));
                bool in = d2 < R2;
                unsigned mk = __ballot_sync(0xffffffffu, in);
                if (mk) {
                    if (!hf) { first = ch * 32 + __ffs(mk) - 1; hf = true; }
                    if (in) {
                        int pos = cnt + __popc(mk & ((1u << lane) - 1u));
                        if (pos < KK) sid[pos] = p;
                    }
                    cnt += __popc(mk);
                }
            }
            for (int i2 = cnt + lane; i2 < KK; i2 += 32) sid[i2] = first;
        }
        GBAR(barid);

        // ---- gather ----
        {
            const float* nx = newxyz + ((long)b * MM + m) * 3;
            float cx = nx[0], cy = nx[1], cz = nx[2];
            int pi = sid[s];
            const float4* frow = (const float4*)(feat + ((long)b * NN + pi) * CC) + part * 4;
#pragma unroll
            for (int q = 0; q < 4; q++) {
                float4 v = frow[q];
                int c0 = 3 + part * 16 + q * 4;
                xin[(c0 + 0) * 32 + s] = v.x;
                xin[(c0 + 1) * 32 + s] = v.y;
                xin[(c0 + 2) * 32 + s] = v.z;
                xin[(c0 + 3) * 32 + s] = v.w;
            }
            if (part == 0) {
                const float* pr = xyz + ((long)b * NN + pi) * 3;
                xin[0 * 32 + s] = pr[0] - cx;
                xin[1 * 32 + s] = pr[1] - cy;
                xin[2 * 32 + s] = pr[2] - cz;
            }
        }
        GBAR(barid);

        // ---- layer 1: 67 -> 64 ----
        {
            int o0 = og * 4;
            ull acc[4][2];
#pragma unroll
            for (int i = 0; i < 4; i++) { acc[i][0] = 0ull; acc[i][1] = 0ull; }
            for (int c = 0; c < CIN; c++) {
                float4 xv = *(const float4*)&xin[c * 32 + s0];
                ulonglong2 wv = *(const ulonglong2*)&sw1[c * 64 + o0];
                ull xb[4] = {pk2(xv.x, xv.x), pk2(xv.y, xv.y), pk2(xv.z, xv.z), pk2(xv.w, xv.w)};
#pragma unroll
                for (int i = 0; i < 4; i++) {
                    acc[i][0] = fma2(xb[i], wv.x, acc[i][0]);
                    acc[i][1] = fma2(xb[i], wv.y, acc[i][1]);
                }
            }
            ull bp0 = *(const ull*)&sb1[o0];
            ull bp1 = *(const ull*)&sb1[o0 + 2];
            float f[4][4];
#pragma unroll
            for (int i = 0; i < 4; i++) {
                upk2(max2(add2(acc[i][0], bp0), 0ull), f[i][0], f[i][1]);
                upk2(max2(add2(acc[i][1], bp1), 0ull), f[i][2], f[i][3]);
            }
#pragma unroll
            for (int j = 0; j < 4; j++)
                *(float4*)&h1[(o0 + j) * 32 + s0] =
                    make_float4(f[0][j], f[1][j], f[2][j], f[3][j]);
        }
        GBAR(barid);

        // ---- layer 2: 64 -> 64 ----
        {
            int o0 = og * 4;
            ull acc[4][2];
#pragma unroll
            for (int i = 0; i < 4; i++) { acc[i][0] = 0ull; acc[i][1] = 0ull; }
            for (int c = 0; c < 64; c++) {
                float4 xv = *(const float4*)&h1[c * 32 + s0];
                ulonglong2 wv = *(const ulonglong2*)&sw2[c * 64 + o0];
                ull xb[4] = {pk2(xv.x, xv.x), pk2(xv.y, xv.y), pk2(xv.z, xv.z), pk2(xv.w, xv.w)};
#pragma unroll
                for (int i = 0; i < 4; i++) {
                    acc[i][0] = fma2(xb[i], wv.x, acc[i][0]);
                    acc[i][1] = fma2(xb[i], wv.y, acc[i][1]);
                }
            }
            ull bp0 = *(const ull*)&sb2[o0];
            ull bp1 = *(const ull*)&sb2[o0 + 2];
            float f[4][4];
#pragma unroll
            for (int i = 0; i < 4; i++) {
                upk2(max2(add2(acc[i][0], bp0), 0ull), f[i][0], f[i][1]);
                upk2(max2(add2(acc[i][1], bp1), 0ull), f[i][2], f[i][3]);
            }
#pragma unroll
            for (int j = 0; j < 4; j++)
                *(float4*)&xin[(o0 + j) * 32 + s0] =
                    make_float4(f[0][j], f[1][j], f[2][j], f[3][j]);
        }
        GBAR(barid);

        // ---- layer 3: 64 -> 128, two 4x4 halves, maxpool ----
        float* op = outf + (long)b * 128 * 1024 + m;
#pragma unroll
        for (int half = 0; half < 2; half++) {
            int oo = og * 8 + half * 4;
            ull a3[4][2];
#pragma unroll
            for (int i = 0; i < 4; i++) { a3[i][0] = 0ull; a3[i][1] = 0ull; }
            for (int c = 0; c < 64; c++) {
                float4 xv = *(const float4*)&xin[c * 32 + s0];
                ulonglong2 wa = *(const ulonglong2*)&sw3[c * 128 + oo];
                ull xb[4] = {pk2(xv.x, xv.x), pk2(xv.y, xv.y), pk2(xv.z, xv.z), pk2(xv.w, xv.w)};
#pragma unroll
                for (int i = 0; i < 4; i++) {
                    a3[i][0] = fma2(xb[i], wa.x, a3[i][0]);
                    a3[i][1] = fma2(xb[i], wa.y, a3[i][1]);
                }
            }
            ull mx[2];
#pragma unroll
            for (int q = 0; q < 2; q++) {
                ull bp = *(const ull*)&sb3[oo + 2 * q];
                ull v = max2(add2(a3[0][q], bp), 0ull);
                v = max2(v, max2(add2(a3[1][q], bp), 0ull));
                v = max2(v, max2(add2(a3[2][q], bp), 0ull));
                v = max2(v, max2(add2(a3[3][q], bp), 0ull));
                mx[q] = v;
            }
#pragma unroll
            for (int off = 1; off < 8; off <<= 1) {
#pragma unroll
                for (int q = 0; q < 2; q++) {
                    ull o = __shfl_xor_sync(0xffffffffu, mx[q], off);
                    mx[q] = max2(mx[q], o);
                }
            }
            if (sg == 0) {
#pragma unroll
                for (int q = 0; q < 2; q++) {
                    float v0, v1;
                    upk2(mx[q], v0, v1);
                    op[(long)(oo + 2 * q) * 1024] = v0;
                    op[(long)(oo + 2 * q + 1) * 1024] = v1;
                }
            }
        }
        GBAR(barid);
    }
}

// ---------------------------------------------------------------------------
extern "C" void kernel_launch(void* const* d_in, const int* in_sizes, int n_in,
                              void* d_out, int out_size) {
    const float* xyz = (const float*)d_in[0];
    const float* feat = (const float*)d_in[1];
    const float* w1 = (const float*)d_in[2];
    const float* b1 = (const float*)d_in[3];
    const float* w2 = (const float*)d_in[4];
    const float* b2 = (const float*)d_in[5];
    const float* w3 = (const float*)d_in[6];
    const float* b3 = (const float*)d_in[7];
    float* out = (float*)d_out;
    float* newxyz = out;                       // (B, M, 3)
    float* outf = out + (long)BB * MM * 3;     // (B, 128, M)

    reset_kernel<<<1, 32>>>();

    int smem = (CIN * 64 + 64 * 64 + 64 * 128 + 64 + 64 + 128 +
                8 * (CIN * 32 + 64 * 32)) * 4;   // 201472 bytes (>= 96KB xyz)
    cudaFuncSetAttribute(fused_kernel, cudaFuncAttributeMaxDynamicSharedMemorySize, smem);
    fused_kernel<<<148, 1024, smem>>>(xyz, feat, w1, b1, w2, b2, w3, b3, newxyz, outf);

    (void)in_sizes; (void)n_in; (void)out_size;
}